// round 5
// baseline (speedup 1.0000x reference)
#include <cuda_runtime.h>
#include <cuda_bf16.h>

#define NUM_USERS 200000
#define NUM_ITEMS 100000
#define NUM_NODES (NUM_USERS + NUM_ITEMS)
#define NUM_EDGES 600000
#define DIM 128
#define BATCH 16384

// ---------------- scratch (static device globals; no runtime allocation) ----
__device__ __align__(16) float g_agg[(size_t)NUM_NODES * DIM];   // masked segment-sum
__device__ __align__(16) unsigned char g_mask[NUM_NODES];        // needed-node mask
__device__ __align__(16) float g_M[DIM * DIM];                   // W^T W (symmetric!)
__device__ __align__(16) float g_v[DIM];                         // W^T b
__device__ float g_c;                                            // b.b

// ---------------- f32x2 helpers ---------------------------------------------
__device__ __forceinline__ unsigned long long pack2(float x, float y) {
    unsigned long long r;
    asm("mov.b64 %0, {%1, %2};" : "=l"(r) : "f"(x), "f"(y));
    return r;
}
__device__ __forceinline__ void fma2(unsigned long long& acc,
                                     unsigned long long a, unsigned long long b) {
    asm("fma.rn.f32x2 %0, %1, %2, %0;" : "+l"(acc) : "l"(a), "l"(b));
}
__device__ __forceinline__ void unpack2(unsigned long long v, float& lo, float& hi) {
    asm("mov.b64 {%0, %1}, %2;" : "=f"(lo), "=f"(hi) : "l"(v));
}

// ---------------- K0 (fused): M = W^T W, v = W^T b, c = b.b, mask = 0 -------
#define MASK16 (NUM_NODES / 16)                 // 18750 int4 slots, exact
#define ZBLOCKS ((MASK16 + 255) / 256)          // 74
__global__ void k_pre(const float* __restrict__ W, const float* __restrict__ b) {
    int blk = blockIdx.x;
    int tid = threadIdx.x;
    if (blk < DIM) {
        int r = blk, c = tid;
        float acc = 0.f;
#pragma unroll 8
        for (int j = 0; j < DIM; j++)
            acc += W[j * DIM + r] * W[j * DIM + c];
        g_M[r * DIM + c] = acc;
        if (blk == 0) {
            float vv = 0.f;
#pragma unroll 8
            for (int j = 0; j < DIM; j++) vv += b[j] * W[j * DIM + c];
            g_v[c] = vv;
            if (tid == 0) {
                float s = 0.f;
#pragma unroll 8
                for (int j = 0; j < DIM; j++) s += b[j] * b[j];
                g_c = s;
            }
        }
    } else {
        int i0 = (blk - DIM) * 256 + tid;
        if (i0 < MASK16) ((int4*)g_mask)[i0] = make_int4(0, 0, 0, 0);
        int i1 = i0 + 128;
        if (i1 < MASK16) ((int4*)g_mask)[i1] = make_int4(0, 0, 0, 0);
    }
}

// ---------------- K1: mark needed nodes, zero their agg rows -----------------
__global__ void k_mark_zero(const int* __restrict__ ui, const int* __restrict__ ii) {
    int t = blockIdx.x * blockDim.x + threadIdx.x;    // 2*BATCH*32 threads
    int ref = t >> 5;
    int sub = t & 31;
    if (ref >= 2 * BATCH) return;
    int node = (ref < BATCH) ? ui[ref] : (NUM_USERS + ii[ref - BATCH]);
    ((float4*)(g_agg + (size_t)node * DIM))[sub] = make_float4(0.f, 0.f, 0.f, 0.f);
    if (sub == 0) g_mask[node] = 1;
}

// ---------------- K2 (fused): scan edges, gather + vectorized scatter-add ----
__global__ void k_edge(const int* __restrict__ src, const int* __restrict__ dst,
                       const float* __restrict__ uemb, const float* __restrict__ iemb) {
    int e = blockIdx.x * blockDim.x + threadIdx.x;
    int lane = threadIdx.x & 31;
    bool pass = false;
    int d = 0, s = 0;
    if (e < NUM_EDGES) {
        d = dst[e];
        pass = (g_mask[d] != 0);
        if (pass) s = src[e];
    }
    unsigned m = __ballot_sync(0xffffffffu, pass);
    while (m) {
        int bit = __ffs(m) - 1;
        m &= m - 1;
        int ds = __shfl_sync(0xffffffffu, d, bit);
        int ss = __shfl_sync(0xffffffffu, s, bit);
        const float* sp = (ss < NUM_USERS)
                            ? (uemb + (size_t)ss * DIM)
                            : (iemb + (size_t)(ss - NUM_USERS) * DIM);
        float4 v = ((const float4*)sp)[lane];
        float* a = g_agg + (size_t)ds * DIM + lane * 4;
        asm volatile("red.global.add.v4.f32 [%0], {%1, %2, %3, %4};"
                     :: "l"(a), "f"(v.x), "f"(v.y), "f"(v.z), "f"(v.w)
                     : "memory");
    }
}

// ---------------- K3: register-tiled fused GEMM + bilinear reduce ------------
// Block: 128 pairs x 128 cols, 512 threads, 4x8 register tile per thread.
// Y = XI @ M^T (M symmetric -> Ms[k][j] = g_M row copy, no transpose).
// v.xi folded into the main k-loop via packed FMA on the a-fragment.
// out[i] = sum_j [ xu[i,j]*(y[i,j]+v[j]) ] + v.xi_i + b.b
#define BPB 128
#define PADI 130   // even: 8B-aligned u64 a-frag loads; 2-way STS conflict only
#define SMEM_K3 ((DIM * DIM + DIM * PADI + DIM) * 4 + DIM * 4)

__global__ void __launch_bounds__(512) k_pairs(
    const int* __restrict__ ui, const int* __restrict__ ii,
    float* __restrict__ out)
{
    extern __shared__ float sm[];
    float* Ms  = sm;                       // [128][128]  k-major (M symmetric)
    float* XIs = Ms + DIM * DIM;           // [128][PADI] XIs[k*PADI + i]
    float* Vv  = XIs + DIM * PADI;         // [128]
    int*   Nd  = (int*)(Vv + DIM);         // [128] user node ids

    int tid  = threadIdx.x;
    int base = blockIdx.x * BPB;
    int warp = tid >> 5, lane = tid & 31;

    // stage M: straight coalesced float4 copy (symmetric => already [k][j])
    for (int idx = tid; idx < DIM * DIM / 4; idx += 512)
        ((float4*)Ms)[idx] = ((const float4*)g_M)[idx];
    if (tid < DIM) { Vv[tid] = g_v[tid]; Nd[tid] = ui[base + tid]; }

    // stage XI transposed: warp w handles rows [w*8, w*8+8).
    // lane loads k = lane + 32c (4 coalesced 128B scalar LDGs per row);
    // STS bank = (2*lane)%32 -> 2-way conflict.
#pragma unroll
    for (int r = 0; r < 8; r++) {
        int g = warp * 8 + r;
        int node = NUM_USERS + __ldg(&ii[base + g]);
        const float* rowp = g_agg + (size_t)node * DIM + lane;
#pragma unroll
        for (int c = 0; c < 4; c++)
            XIs[(lane + 32 * c) * PADI + g] = rowp[32 * c];
    }
    __syncthreads();

    int tx = tid & 15, ty = tid >> 4;     // ty: 0..31
    int j0 = tx * 8, i0 = ty * 4;

    unsigned long long acc[4][4];         // [i][jpair]
    unsigned long long vacc[2];           // v.xi for 4 i's
#pragma unroll
    for (int i = 0; i < 4; i++)
#pragma unroll
        for (int jp = 0; jp < 4; jp++) acc[i][jp] = 0ull;
    vacc[0] = vacc[1] = 0ull;

#pragma unroll 4
    for (int k = 0; k < DIM; k++) {
        // a-fragment: 4 xi values for pairs i0..i0+3 (two 8B loads, broadcast)
        unsigned long long au0 = *(const unsigned long long*)&XIs[k * PADI + i0];
        unsigned long long au1 = *(const unsigned long long*)&XIs[k * PADI + i0 + 2];
        // b-fragment: 8 M values (two 16B loads)
        ulonglong2 b0 = *(const ulonglong2*)&Ms[k * DIM + j0];
        ulonglong2 b1 = *(const ulonglong2*)&Ms[k * DIM + j0 + 4];

        // fold v.xi
        float vk = Vv[k];
        unsigned long long vkd = pack2(vk, vk);
        fma2(vacc[0], au0, vkd);
        fma2(vacc[1], au1, vkd);

        float av[4];
        unpack2(au0, av[0], av[1]);
        unpack2(au1, av[2], av[3]);
#pragma unroll
        for (int i = 0; i < 4; i++) {
            unsigned long long ad = pack2(av[i], av[i]);
            fma2(acc[i][0], ad, b0.x);
            fma2(acc[i][1], ad, b0.y);
            fma2(acc[i][2], ad, b1.x);
            fma2(acc[i][3], ad, b1.y);
        }
    }

    // epilogue: p_i(tx) = sum_{q in tile} xu[i][j0+q]*(y+v)[j0+q];
    // reduce over the 16 tx lanes (xor offs 1..8 stay within a half-warp)
    float vj[8];
#pragma unroll
    for (int q = 0; q < 8; q++) vj[q] = Vv[j0 + q];

    float cc = g_c;
#pragma unroll
    for (int r = 0; r < 4; r++) {
        int i = i0 + r;
        const float* xup = g_agg + (size_t)Nd[i] * DIM + j0;
        float4 xu0 = *(const float4*)xup;
        float4 xu1 = *(const float4*)(xup + 4);
        float xuv[8] = {xu0.x, xu0.y, xu0.z, xu0.w, xu1.x, xu1.y, xu1.z, xu1.w};
        float y[8];
#pragma unroll
        for (int jp = 0; jp < 4; jp++) unpack2(acc[r][jp], y[2 * jp], y[2 * jp + 1]);
        float p = 0.f;
#pragma unroll
        for (int q = 0; q < 8; q++)
            p += xuv[q] * (y[q] + vj[q]);
#pragma unroll
        for (int off = 1; off < 16; off <<= 1)
            p += __shfl_xor_sync(0xffffffffu, p, off);
        if (tx == 0) {
            float d0, d1;
            unpack2(vacc[r >> 1], d0, d1);
            float vdot = (r & 1) ? d1 : d0;
            out[base + i] = p + vdot + cc;
        }
    }
}

// ---------------- launch ----------------------------------------------------
extern "C" void kernel_launch(void* const* d_in, const int* in_sizes, int n_in,
                              void* d_out, int out_size) {
    const int*   ui   = (const int*)d_in[0];
    const int*   ii   = (const int*)d_in[1];
    const float* uemb = (const float*)d_in[2];
    const float* iemb = (const float*)d_in[3];
    const float* W    = (const float*)d_in[4];
    const float* b    = (const float*)d_in[5];
    const int*   ei   = (const int*)d_in[6];
    const int*   src  = ei;
    const int*   dst  = ei + NUM_EDGES;
    float*       out  = (float*)d_out;

    cudaFuncSetAttribute(k_pairs, cudaFuncAttributeMaxDynamicSharedMemorySize, SMEM_K3);

    k_pre<<<DIM + ZBLOCKS, DIM>>>(W, b);
    k_mark_zero<<<(2 * BATCH * 32) / 256, 256>>>(ui, ii);
    k_edge<<<(NUM_EDGES + 255) / 256, 256>>>(src, dst, uemb, iemb);
    k_pairs<<<BATCH / BPB, 512, SMEM_K3>>>(ui, ii, out);
}

// round 7
// speedup vs baseline: 1.4554x; 1.4554x over previous
#include <cuda_runtime.h>
#include <cuda_bf16.h>
#include <cstdint>

#define NUM_USERS 200000
#define NUM_ITEMS 100000
#define NUM_NODES (NUM_USERS + NUM_ITEMS)
#define NUM_EDGES 600000
#define DIM 128
#define BATCH 16384
#define BPB 128
#define S 132   // smem row stride (floats): conflict-free fragment access

// ---------------- scratch (static device globals) ---------------------------
__device__ __align__(16) float g_agg[(size_t)NUM_NODES * DIM];
__device__ __align__(16) unsigned char g_mask[NUM_NODES];
__device__ __align__(16) float g_M[DIM * DIM];      // W^T W, tf32-rounded (symmetric)
__device__ __align__(16) float g_v[DIM];            // W^T b (fp32)
__device__ float g_c;                               // b.b

__device__ __forceinline__ float tf32r(float x) {
    unsigned u = __float_as_uint(x);
    u = (u + 0x1000u) & 0xFFFFE000u;
    return __uint_as_float(u);
}

// ---------------- K0: M = W^T W (tf32), v = W^T b, c = b.b, mask = 0 --------
#define MASK16 (NUM_NODES / 16)
#define ZBLOCKS ((MASK16 + 255) / 256)
__global__ void k_pre(const float* __restrict__ W, const float* __restrict__ b) {
    int blk = blockIdx.x, tid = threadIdx.x;
    if (blk < DIM) {
        int r = blk, c = tid;
        float acc = 0.f;
#pragma unroll 8
        for (int j = 0; j < DIM; j++)
            acc += W[j * DIM + r] * W[j * DIM + c];
        g_M[r * DIM + c] = tf32r(acc);
        if (blk == 0) {
            float vv = 0.f;
#pragma unroll 8
            for (int j = 0; j < DIM; j++) vv += b[j] * W[j * DIM + c];
            g_v[c] = vv;
            if (tid == 0) {
                float s = 0.f;
#pragma unroll 8
                for (int j = 0; j < DIM; j++) s += b[j] * b[j];
                g_c = s;
            }
        }
    } else {
        int i0 = (blk - DIM) * 256 + tid;
        if (i0 < MASK16) ((int4*)g_mask)[i0] = make_int4(0, 0, 0, 0);
        int i1 = i0 + 128;
        if (i1 < MASK16) ((int4*)g_mask)[i1] = make_int4(0, 0, 0, 0);
    }
}

// ---------------- K1: mark needed nodes, zero their agg rows -----------------
__global__ void k_mark_zero(const int* __restrict__ ui, const int* __restrict__ ii) {
    int t = blockIdx.x * blockDim.x + threadIdx.x;
    int ref = t >> 5, sub = t & 31;
    if (ref >= 2 * BATCH) return;
    int node = (ref < BATCH) ? ui[ref] : (NUM_USERS + ii[ref - BATCH]);
    ((float4*)(g_agg + (size_t)node * DIM))[sub] = make_float4(0.f, 0.f, 0.f, 0.f);
    if (sub == 0) g_mask[node] = 1;
}

// ---------------- K2: scan edges, gather + vectorized scatter-add ------------
__global__ void k_edge(const int* __restrict__ src, const int* __restrict__ dst,
                       const float* __restrict__ uemb, const float* __restrict__ iemb) {
    int e = blockIdx.x * blockDim.x + threadIdx.x;
    int lane = threadIdx.x & 31;
    bool pass = false;
    int d = 0, s = 0;
    if (e < NUM_EDGES) {
        d = dst[e];
        pass = (g_mask[d] != 0);
        if (pass) s = src[e];
    }
    unsigned m = __ballot_sync(0xffffffffu, pass);
    while (m) {
        int bit = __ffs(m) - 1;
        m &= m - 1;
        int ds = __shfl_sync(0xffffffffu, d, bit);
        int ss = __shfl_sync(0xffffffffu, s, bit);
        const float* sp = (ss < NUM_USERS)
                            ? (uemb + (size_t)ss * DIM)
                            : (iemb + (size_t)(ss - NUM_USERS) * DIM);
        float4 v = ((const float4*)sp)[lane];
        float* a = g_agg + (size_t)ds * DIM + lane * 4;
        asm volatile("red.global.add.v4.f32 [%0], {%1, %2, %3, %4};"
                     :: "l"(a), "f"(v.x), "f"(v.y), "f"(v.z), "f"(v.w)
                     : "memory");
    }
}

// ---------------- K3: mma.sync tf32 GEMM + fused bilinear epilogue -----------
// Per block (128 pairs): Y[128,128] = XI @ M (tf32 HMMA), then
// out_i = sum_j xu_ij * Y_ij + v.xu_i + v.xi_i + b.b
// 512 threads = 4(m) x 4(n) warps, 32x32 warp tile = 2x4 m16n8k8 subtiles.
#define MS_OFF   0
#define XI_OFF   (DIM * S * 4)
#define XU_OFF   (2 * DIM * S * 4)
#define VXI_OFF  (3 * DIM * S * 4)
#define VXU_OFF  (VXI_OFF + 512)
#define PART_OFF (VXU_OFF + 512)
#define SMEM_K3  (PART_OFF + 2048)

__global__ void __launch_bounds__(512) k_pairs(
    const int* __restrict__ ui, const int* __restrict__ ii,
    float* __restrict__ out)
{
    extern __shared__ char sm[];
    float* Msm  = (float*)(sm + MS_OFF);    // Msm[j][k] = M[j][k] (= B[k][j], symmetric)
    float* XIs  = (float*)(sm + XI_OFF);    // XIs[i][k], tf32-rounded
    float* XUs  = (float*)(sm + XU_OFF);    // XUs[i][k], fp32
    float* Vxi  = (float*)(sm + VXI_OFF);
    float* Vxu  = (float*)(sm + VXU_OFF);
    float* Part = (float*)(sm + PART_OFF);  // [128][4]

    int tid = threadIdx.x, warp = tid >> 5, lane = tid & 31;
    int base = blockIdx.x * BPB;
    int g = lane >> 2, t = lane & 3;        // quad layout for mma fragments

    // stage M with restride (row r of g_M -> Msm row r); float4, conflict-free
    for (int idx = tid; idx < DIM * DIM / 4; idx += 512) {
        int r = idx >> 5, c4 = idx & 31;
        *(float4*)&Msm[r * S + 4 * c4] = ((const float4*)g_M)[idx];
    }

    // stage XI (tf32) + XU (fp32), fold v.xi / v.xu; warp w -> rows [8w, 8w+8)
#pragma unroll
    for (int r = 0; r < 8; r++) {
        int row = warp * 8 + r;
        int ndi = NUM_USERS + __ldg(&ii[base + row]);
        int ndu = __ldg(&ui[base + row]);
        const float* rpi = g_agg + (size_t)ndi * DIM;
        const float* rpu = g_agg + (size_t)ndu * DIM;
        float vdi = 0.f, vdu = 0.f;
#pragma unroll
        for (int c = 0; c < 4; c++) {
            int k = lane + 32 * c;
            float vk = __ldg(&g_v[k]);
            float xi = __ldg(&rpi[k]);
            float xu = __ldg(&rpu[k]);
            vdi += xi * vk;
            vdu += xu * vk;
            XIs[row * S + k] = tf32r(xi);
            XUs[row * S + k] = xu;
        }
#pragma unroll
        for (int o = 16; o; o >>= 1) {
            vdi += __shfl_xor_sync(0xffffffffu, vdi, o);
            vdu += __shfl_xor_sync(0xffffffffu, vdu, o);
        }
        if (lane == 0) { Vxi[row] = vdi; Vxu[row] = vdu; }
    }
    __syncthreads();

    // warp tile: rows m0..m0+31, cols j0..j0+31
    int m0 = (warp & 3) * 32, j0 = (warp >> 2) * 32;
    float acc[2][4][4];
#pragma unroll
    for (int mi = 0; mi < 2; mi++)
#pragma unroll
        for (int ni = 0; ni < 4; ni++)
#pragma unroll
            for (int q = 0; q < 4; q++) acc[mi][ni][q] = 0.f;

#pragma unroll
    for (int k0 = 0; k0 < DIM; k0 += 8) {
        uint32_t a[2][4], b[4][2];
#pragma unroll
        for (int mi = 0; mi < 2; mi++) {
            const float* ap = XIs + (m0 + 16 * mi + g) * S + k0 + t;
            a[mi][0] = __float_as_uint(ap[0]);
            a[mi][1] = __float_as_uint(ap[8 * S]);
            a[mi][2] = __float_as_uint(ap[4]);
            a[mi][3] = __float_as_uint(ap[8 * S + 4]);
        }
#pragma unroll
        for (int ni = 0; ni < 4; ni++) {
            const float* bp = Msm + (j0 + 8 * ni + g) * S + k0 + t;
            b[ni][0] = __float_as_uint(bp[0]);
            b[ni][1] = __float_as_uint(bp[4]);
        }
#pragma unroll
        for (int mi = 0; mi < 2; mi++)
#pragma unroll
            for (int ni = 0; ni < 4; ni++)
                asm volatile(
                    "mma.sync.aligned.m16n8k8.row.col.f32.tf32.tf32.f32 "
                    "{%0,%1,%2,%3}, {%4,%5,%6,%7}, {%8,%9}, {%0,%1,%2,%3};"
                    : "+f"(acc[mi][ni][0]), "+f"(acc[mi][ni][1]),
                      "+f"(acc[mi][ni][2]), "+f"(acc[mi][ni][3])
                    : "r"(a[mi][0]), "r"(a[mi][1]), "r"(a[mi][2]), "r"(a[mi][3]),
                      "r"(b[ni][0]), "r"(b[ni][1]));
    }

    // epilogue: p_row = sum over this warp's 32 j of xu * y; reduce over quad t
    int nw = warp >> 2;
#pragma unroll
    for (int mi = 0; mi < 2; mi++) {
        int r_lo = m0 + 16 * mi + g;
        int r_hi = r_lo + 8;
        float plo = 0.f, phi = 0.f;
#pragma unroll
        for (int ni = 0; ni < 4; ni++) {
            int j = j0 + 8 * ni + 2 * t;
            float2 xul = *(const float2*)&XUs[r_lo * S + j];
            float2 xuh = *(const float2*)&XUs[r_hi * S + j];
            plo += xul.x * acc[mi][ni][0] + xul.y * acc[mi][ni][1];
            phi += xuh.x * acc[mi][ni][2] + xuh.y * acc[mi][ni][3];
        }
        plo += __shfl_xor_sync(0xffffffffu, plo, 1);
        plo += __shfl_xor_sync(0xffffffffu, plo, 2);
        phi += __shfl_xor_sync(0xffffffffu, phi, 1);
        phi += __shfl_xor_sync(0xffffffffu, phi, 2);
        if (t == 0) {
            Part[r_lo * 4 + nw] = plo;
            Part[r_hi * 4 + nw] = phi;
        }
    }
    __syncthreads();

    if (tid < BPB) {
        float r = Part[tid * 4 + 0] + Part[tid * 4 + 1]
                + Part[tid * 4 + 2] + Part[tid * 4 + 3];
        out[base + tid] = r + Vxi[tid] + Vxu[tid] + g_c;
    }
}

// ---------------- launch ----------------------------------------------------
extern "C" void kernel_launch(void* const* d_in, const int* in_sizes, int n_in,
                              void* d_out, int out_size) {
    const int*   ui   = (const int*)d_in[0];
    const int*   ii   = (const int*)d_in[1];
    const float* uemb = (const float*)d_in[2];
    const float* iemb = (const float*)d_in[3];
    const float* W    = (const float*)d_in[4];
    const float* b    = (const float*)d_in[5];
    const int*   ei   = (const int*)d_in[6];
    const int*   src  = ei;
    const int*   dst  = ei + NUM_EDGES;
    float*       out  = (float*)d_out;

    cudaFuncSetAttribute(k_pairs, cudaFuncAttributeMaxDynamicSharedMemorySize, SMEM_K3);

    k_pre<<<DIM + ZBLOCKS, DIM>>>(W, b);
    k_mark_zero<<<(2 * BATCH * 32) / 256, 256>>>(ui, ii);
    k_edge<<<(NUM_EDGES + 255) / 256, 256>>>(src, dst, uemb, iemb);
    k_pairs<<<BATCH / BPB, 512, SMEM_K3>>>(ui, ii, out);
}